// round 11
// baseline (speedup 1.0000x reference)
#include <cuda_runtime.h>
#include <cuda_fp16.h>
#include <cuda_bf16.h>
#include <cstdint>

#define N_TOKENS 32
#define IN_F     4096
#define OUT_F    11008
#define TILE_M   64
#define KC       64
#define NCHUNK   (IN_F / KC)       // 64
#define THREADS  128               // 4 warps

// SMEM: double-buffered A (64x64 fp16, 128B rows) + B (32x64 fp16)
#define A_BYTES  (TILE_M * 128)    // 8192
#define B_BYTES  (N_TOKENS * 128)  // 4096
#define OFF_A0   0
#define OFF_B0   (A_BYTES)
#define OFF_A1   (A_BYTES + B_BYTES)
#define OFF_B1   (OFF_A1 + A_BYTES)
#define SMEM_BYTES (2 * (A_BYTES + B_BYTES) + 1024)   // 25600

// runtime dtype flags, written by detect_kernel
__device__ int g_qint32;   // 1: qweight is int32, 0: int8
__device__ int g_xdt;      // 0: fp32, 1: fp16, 2: bf16  (x / scales / bias / out)

// ---------------- helpers ----------------
__device__ __forceinline__ uint32_t smem_u32(const void* p) {
    uint32_t a;
    asm("{ .reg .u64 t; cvta.to.shared.u64 t, %1; cvt.u32.u64 %0, t; }" : "=r"(a) : "l"(p));
    return a;
}
__device__ __forceinline__ uint32_t swz(uint32_t off) {   // SW128: Swizzle<3,4,3>
    return off ^ ((off >> 3) & 0x70);
}
__device__ __forceinline__ void ldsm_x4(uint32_t& r0, uint32_t& r1, uint32_t& r2,
                                        uint32_t& r3, uint32_t addr) {
    asm volatile("ldmatrix.sync.aligned.m8n8.x4.shared.b16 {%0,%1,%2,%3}, [%4];"
                 : "=r"(r0), "=r"(r1), "=r"(r2), "=r"(r3) : "r"(addr));
}
__device__ __forceinline__ void mma16816(float* c, uint32_t a0, uint32_t a1,
                                         uint32_t a2, uint32_t a3,
                                         uint32_t b0, uint32_t b1) {
    asm volatile(
        "mma.sync.aligned.m16n8k16.row.col.f32.f16.f16.f32 "
        "{%0,%1,%2,%3}, {%4,%5,%6,%7}, {%8,%9}, {%0,%1,%2,%3};"
        : "+f"(c[0]), "+f"(c[1]), "+f"(c[2]), "+f"(c[3])
        : "r"(a0), "r"(a1), "r"(a2), "r"(a3), "r"(b0), "r"(b1));
}

// ---------------- dtype detection (1 block, deterministic) ----------------
// qweight buffer is >= OUT_F*IN_F elements of >= 1 byte; x >= N_TOKENS*IN_F
// elements of >= 2 bytes. All scans below stay within the minimal-width bound.
__global__ void detect_kernel(const void* x, const void* qw) {
    if (threadIdx.x != 0) return;

    // qweight: int32 iff the first 64 words all look like small ints.
    // (64 words = 256 bytes, safely within even the int8 interpretation's
    //  45MB. Random int8 bytes reinterpreted as int32 pass the [-128,127]
    //  test with prob ~2^-24 per word -> 2^-1536 over 64 words.)
    const int* qi = (const int*)qw;
    int small = 1;
    for (int i = 0; i < 64; ++i) {
        int v = qi[i];
        if (v < -128 || v > 127) small = 0;
    }
    g_qint32 = small;

    // x: score fp32 / fp16 / bf16 interpretations of the first 512 bytes
    // (within bounds for the narrowest 2-byte interpretation: 256KB min).
    const uint32_t* xw = (const uint32_t*)x;
    float m[3] = {0.f, 0.f, 0.f};
    for (int i = 0; i < 128; ++i) {
        uint32_t w = xw[i];
        float f = __uint_as_float(w);
        float a = fabsf(f);
        if (!isfinite(a) || a > 16.f) a = 16.f;
        if (a < 1e-6f) a = 1e-6f;
        m[0] += a;
        for (int hsel = 0; hsel < 2; ++hsel) {
            uint32_t hbits = (w >> (16 * hsel)) & 0xFFFFu;
            float fh = __half2float(__ushort_as_half((unsigned short)hbits));
            float ah = fabsf(fh);
            if (!isfinite(ah) || ah > 16.f) ah = 16.f;
            if (ah < 1e-6f) ah = 1e-6f;
            m[1] += 0.5f * ah;
            float fb = __uint_as_float(hbits << 16);
            float ab = fabsf(fb);
            if (!isfinite(ab) || ab > 16.f) ab = 16.f;
            if (ab < 1e-6f) ab = 1e-6f;
            m[2] += 0.5f * ab;
        }
    }
    int best = 0;
    float bd = 1e30f;
    for (int k = 0; k < 3; ++k) {
        float mm = m[k] * (1.0f / 128.0f);
        float d = fabsf(logf(mm / 0.798f));   // E|N(0,1)| = 0.798
        if (d < bd) { bd = d; best = k; }
    }
    g_xdt = best;
}

// ---------------- main kernel ----------------
__global__ void __launch_bounds__(THREADS, 2)
qlin_mma_kernel(const void* __restrict__ xv,
                const void* __restrict__ qwv,
                const void* __restrict__ scalesv,
                const void* __restrict__ biasv,
                void* __restrict__ outv)
{
    extern __shared__ char smem_raw[];
    const uint32_t sb = (smem_u32(smem_raw) + 1023u) & ~1023u;
    const uint32_t aoff[2] = {sb + OFF_A0, sb + OFF_A1};
    const uint32_t boff[2] = {sb + OFF_B0, sb + OFF_B1};

    const int q32 = g_qint32;     // uniform across grid
    const int xdt = g_xdt;        // uniform across grid

    const int tid  = threadIdx.x;
    const int wid  = tid >> 5;
    const int lane = tid & 31;
    const int row0 = blockIdx.x * TILE_M;

    // staging roles
    const int r = tid >> 1, h = tid & 1;     // W: row r (0..63), half h (32 weights)
    const int tok = tid >> 2, seg = tid & 3; // X: token, 16-element segment

    // per-dtype base pointers (element offsets identical; widths differ)
    const int8_t* w8base  = (const int8_t*)qwv + (size_t)(row0 + r) * IN_F + h * 32;
    const int*    w32base = (const int*)qwv    + (size_t)(row0 + r) * IN_F + h * 32;
    const __half* x16base = (const __half*)xv  + (size_t)tok * IN_F + seg * 16;
    const float*  x32base = (const float*)xv   + (size_t)tok * IN_F + seg * 16;

    // raw prefetch buffers (worst case: W 8x uint4, X 4x uint4), depth 2
    uint4 wraw[2][8];
    uint4 xraw[2][4];

    auto load_w = [&](int s, int c) {
        if (q32) {
            const uint4* p = (const uint4*)(w32base + c * KC);
#pragma unroll
            for (int j = 0; j < 8; ++j) wraw[s][j] = p[j];
        } else {
            const uint4* p = (const uint4*)(w8base + c * KC);
            wraw[s][0] = p[0];
            wraw[s][1] = p[1];
        }
    };
    auto load_x = [&](int s, int c) {
        if (xdt == 0) {
            const uint4* p = (const uint4*)(x32base + (size_t)c * KC);
#pragma unroll
            for (int j = 0; j < 4; ++j) xraw[s][j] = p[j];
        } else {  // fp16 / bf16: same byte width
            const uint4* p = (const uint4*)(x16base + (size_t)c * KC);
            xraw[s][0] = p[0];
            xraw[s][1] = p[1];
        }
    };

    load_w(0, 0); load_x(0, 0);
    load_w(1, 1); load_x(1, 1);

    float acc[4][4];
#pragma unroll
    for (int i = 0; i < 4; ++i)
#pragma unroll
        for (int j = 0; j < 4; ++j) acc[i][j] = 0.0f;

    // ldmatrix per-lane addressing
    const int am = lane >> 3;
    const uint32_t a_noswz =
        (uint32_t)((wid * 16 + (am & 1) * 8 + (lane & 7)) * 128 + (am >> 1) * 16);
    const uint32_t b_row_local =
        (uint32_t)(((am >> 1) * 8 + (lane & 7)) * 128 + (am & 1) * 16);

    const uint32_t a_sts_base = (uint32_t)(r * 128 + h * 64);
    const uint32_t b_sts_base = (uint32_t)(tok * 128 + seg * 32);

#pragma unroll 1
    for (int c = 0; c < NCHUNK; ++c) {
        const int s = c & 1;

        // ---- W: raw -> packed int8 bytes -> exact fp16 ----
        const uint32_t* wr = (const uint32_t*)wraw[s];
        uint32_t pk[8];
        if (q32) {
#pragma unroll
            for (int i = 0; i < 8; ++i) {   // low byte of int32 == int8 two's complement
                uint32_t t1, t2;
                asm("prmt.b32 %0, %1, %2, 0x0040;" : "=r"(t1) : "r"(wr[4 * i]),     "r"(wr[4 * i + 1]));
                asm("prmt.b32 %0, %1, %2, 0x0040;" : "=r"(t2) : "r"(wr[4 * i + 2]), "r"(wr[4 * i + 3]));
                asm("prmt.b32 %0, %1, %2, 0x5410;" : "=r"(pk[i]) : "r"(t1), "r"(t2));
            }
        } else {
#pragma unroll
            for (int i = 0; i < 8; ++i) pk[i] = wr[i];
        }
        uint32_t o2[16];
#pragma unroll
        for (int i = 0; i < 8; ++i) {   // u = b^0x80; half = (0x6400|u) - 1152
            uint32_t u = pk[i] ^ 0x80808080u;
            uint32_t lo, hi;
            asm("prmt.b32 %0, %1, %2, 0x5140;" : "=r"(lo) : "r"(u), "r"(0x64646464u));
            asm("prmt.b32 %0, %1, %2, 0x7362;" : "=r"(hi) : "r"(u), "r"(0x64646464u));
            asm("sub.rn.f16x2 %0, %1, %2;" : "=r"(o2[2 * i])     : "r"(lo), "r"(0x64806480u));
            asm("sub.rn.f16x2 %0, %1, %2;" : "=r"(o2[2 * i + 1]) : "r"(hi), "r"(0x64806480u));
        }
#pragma unroll
        for (int q = 0; q < 4; ++q) {
            uint32_t addr = aoff[s] + swz(a_sts_base + q * 16);
            asm volatile("st.shared.v4.b32 [%0], {%1,%2,%3,%4};"
                         :: "r"(addr), "r"(o2[4 * q]), "r"(o2[4 * q + 1]),
                            "r"(o2[4 * q + 2]), "r"(o2[4 * q + 3]) : "memory");
        }

        // ---- X: raw -> fp16x2 ----
        uint32_t xb[8];
        const uint32_t* xr = (const uint32_t*)xraw[s];
        if (xdt == 1) {
#pragma unroll
            for (int j = 0; j < 8; ++j) xb[j] = xr[j];
        } else if (xdt == 0) {
#pragma unroll
            for (int j = 0; j < 8; ++j) {
                __half2 hp = __floats2half2_rn(__uint_as_float(xr[2 * j]),
                                               __uint_as_float(xr[2 * j + 1]));
                xb[j] = *(uint32_t*)&hp;
            }
        } else {  // bf16x2 word -> f16x2
#pragma unroll
            for (int j = 0; j < 8; ++j) {
                uint32_t w = xr[j];
                float f0 = __uint_as_float(w << 16);
                float f1 = __uint_as_float(w & 0xFFFF0000u);
                __half2 hp = __floats2half2_rn(f0, f1);
                xb[j] = *(uint32_t*)&hp;
            }
        }
#pragma unroll
        for (int j = 0; j < 2; ++j) {
            uint32_t addr = boff[s] + swz(b_sts_base + j * 16);
            asm volatile("st.shared.v4.b32 [%0], {%1,%2,%3,%4};"
                         :: "r"(addr), "r"(xb[4 * j]), "r"(xb[4 * j + 1]),
                            "r"(xb[4 * j + 2]), "r"(xb[4 * j + 3]) : "memory");
        }

        __syncthreads();   // STS(c) visible; transitively fences buffer reuse

        // prefetch chunk c+2 into the register set just consumed
        if (c + 2 < NCHUNK) { load_w(s, c + 2); load_x(s, c + 2); }

        // ---- compute: 4 k-steps of m16n8k16 over 4 n-tiles ----
        const uint32_t ab = aoff[s], bb = boff[s];
#pragma unroll
        for (int ks = 0; ks < 4; ++ks) {
            const uint32_t kbyte = (uint32_t)(ks * 32);
            uint32_t a0, a1, a2, a3;
            ldsm_x4(a0, a1, a2, a3, ab + swz(a_noswz + kbyte));
            uint32_t b0, b1, b2, b3;
            ldsm_x4(b0, b1, b2, b3, bb + swz(b_row_local + kbyte));            // tokens 0-15
            uint32_t b4, b5, b6, b7;
            ldsm_x4(b4, b5, b6, b7, bb + swz(b_row_local + 16 * 128 + kbyte)); // tokens 16-31
            mma16816(acc[0], a0, a1, a2, a3, b0, b1);
            mma16816(acc[1], a0, a1, a2, a3, b2, b3);
            mma16816(acc[2], a0, a1, a2, a3, b4, b5);
            mma16816(acc[3], a0, a1, a2, a3, b6, b7);
        }
    }

    // ---- epilogue: scale * acc + bias ----
    const int g = lane >> 2, tig = lane & 3;
    const int o0 = row0 + wid * 16 + g;
    const int o1 = o0 + 8;

    float s0, s1, bi0, bi1;
    if (xdt == 0) {
        s0  = ((const float*)scalesv)[o0]; s1  = ((const float*)scalesv)[o1];
        bi0 = ((const float*)biasv)[o0];   bi1 = ((const float*)biasv)[o1];
    } else if (xdt == 1) {
        s0  = __half2float(((const __half*)scalesv)[o0]);
        s1  = __half2float(((const __half*)scalesv)[o1]);
        bi0 = __half2float(((const __half*)biasv)[o0]);
        bi1 = __half2float(((const __half*)biasv)[o1]);
    } else {
        s0  = __uint_as_float(((uint32_t)((const unsigned short*)scalesv)[o0]) << 16);
        s1  = __uint_as_float(((uint32_t)((const unsigned short*)scalesv)[o1]) << 16);
        bi0 = __uint_as_float(((uint32_t)((const unsigned short*)biasv)[o0]) << 16);
        bi1 = __uint_as_float(((uint32_t)((const unsigned short*)biasv)[o1]) << 16);
    }

#pragma unroll
    for (int nt = 0; nt < 4; ++nt) {
        const int t0 = nt * 8 + tig * 2;
        float v00 = acc[nt][0] * s0 + bi0;
        float v01 = acc[nt][1] * s0 + bi0;
        float v10 = acc[nt][2] * s1 + bi1;
        float v11 = acc[nt][3] * s1 + bi1;
        size_t i00 = (size_t)t0 * OUT_F + o0, i01 = i00 + OUT_F;
        size_t i10 = (size_t)t0 * OUT_F + o1, i11 = i10 + OUT_F;
        if (xdt == 0) {
            float* o = (float*)outv;
            o[i00] = v00; o[i01] = v01; o[i10] = v10; o[i11] = v11;
        } else if (xdt == 1) {
            __half* o = (__half*)outv;
            o[i00] = __float2half(v00); o[i01] = __float2half(v01);
            o[i10] = __float2half(v10); o[i11] = __float2half(v11);
        } else {
            __nv_bfloat16* o = (__nv_bfloat16*)outv;
            o[i00] = __float2bfloat16(v00); o[i01] = __float2bfloat16(v01);
            o[i10] = __float2bfloat16(v10); o[i11] = __float2bfloat16(v11);
        }
    }
}

extern "C" void kernel_launch(void* const* d_in, const int* in_sizes, int n_in,
                              void* d_out, int out_size) {
    const void* x      = d_in[0];
    const void* qw     = d_in[1];
    const void* scales = d_in[2];
    const void* bias   = d_in[3];

    detect_kernel<<<1, 32>>>(x, qw);
    dim3 grid(OUT_F / TILE_M);   // 172 CTAs, 64 output rows each
    qlin_mma_kernel<<<grid, THREADS, SMEM_BYTES>>>(x, qw, scales, bias, d_out);
}

// round 12
// speedup vs baseline: 2.0288x; 2.0288x over previous
#include <cuda_runtime.h>
#include <cuda_fp16.h>
#include <cuda_bf16.h>
#include <cstdint>

#define N_TOKENS 32
#define IN_F     4096
#define OUT_F    11008
#define KC       64
#define NCHUNK   (IN_F / KC)       // 64
#define THREADS  128               // 4 warps

// ---- fast-path (int32 W, fp32 x) config: TILE_M = 32 ----
#define FTILE_M  32
#define FA_BYTES (FTILE_M * 128)   // 4096
#define FB_BYTES (N_TOKENS * 128)  // 4096
#define F_OFF_A0 0
#define F_OFF_B0 (FA_BYTES)
#define F_OFF_A1 (FA_BYTES + FB_BYTES)
#define F_OFF_B1 (F_OFF_A1 + FA_BYTES)
#define F_SMEM   (2 * (FA_BYTES + FB_BYTES) + 1024)   // 17408

// ---- generic fallback config: TILE_M = 64 ----
#define TILE_M   64
#define A_BYTES  (TILE_M * 128)
#define B_BYTES  (N_TOKENS * 128)
#define OFF_A0   0
#define OFF_B0   (A_BYTES)
#define OFF_A1   (A_BYTES + B_BYTES)
#define OFF_B1   (OFF_A1 + A_BYTES)
#define SMEM_BYTES (2 * (A_BYTES + B_BYTES) + 1024)

// runtime dtype flags
__device__ int g_qint32;   // 1: qweight int32, 0: int8
__device__ int g_xdt;      // 0: fp32, 1: fp16, 2: bf16

// ---------------- helpers ----------------
__device__ __forceinline__ uint32_t smem_u32(const void* p) {
    uint32_t a;
    asm("{ .reg .u64 t; cvta.to.shared.u64 t, %1; cvt.u32.u64 %0, t; }" : "=r"(a) : "l"(p));
    return a;
}
__device__ __forceinline__ uint32_t swz(uint32_t off) {   // SW128: Swizzle<3,4,3>
    return off ^ ((off >> 3) & 0x70);
}
__device__ __forceinline__ void ldsm_x4(uint32_t& r0, uint32_t& r1, uint32_t& r2,
                                        uint32_t& r3, uint32_t addr) {
    asm volatile("ldmatrix.sync.aligned.m8n8.x4.shared.b16 {%0,%1,%2,%3}, [%4];"
                 : "=r"(r0), "=r"(r1), "=r"(r2), "=r"(r3) : "r"(addr));
}
__device__ __forceinline__ void mma16816(float* c, uint32_t a0, uint32_t a1,
                                         uint32_t a2, uint32_t a3,
                                         uint32_t b0, uint32_t b1) {
    asm volatile(
        "mma.sync.aligned.m16n8k16.row.col.f32.f16.f16.f32 "
        "{%0,%1,%2,%3}, {%4,%5,%6,%7}, {%8,%9}, {%0,%1,%2,%3};"
        : "+f"(c[0]), "+f"(c[1]), "+f"(c[2]), "+f"(c[3])
        : "r"(a0), "r"(a1), "r"(a2), "r"(a3), "r"(b0), "r"(b1));
}

// ---------------- dtype detection (1 block, deterministic) ----------------
__global__ void detect_kernel(const void* x, const void* qw) {
    if (threadIdx.x != 0) return;
    const int* qi = (const int*)qw;
    int small = 1;
    for (int i = 0; i < 64; ++i) {
        int v = qi[i];
        if (v < -128 || v > 127) small = 0;
    }
    g_qint32 = small;

    const uint32_t* xw = (const uint32_t*)x;
    float m[3] = {0.f, 0.f, 0.f};
    for (int i = 0; i < 128; ++i) {
        uint32_t w = xw[i];
        float a = fabsf(__uint_as_float(w));
        if (!isfinite(a) || a > 16.f) a = 16.f;
        if (a < 1e-6f) a = 1e-6f;
        m[0] += a;
        for (int hsel = 0; hsel < 2; ++hsel) {
            uint32_t hbits = (w >> (16 * hsel)) & 0xFFFFu;
            float ah = fabsf(__half2float(__ushort_as_half((unsigned short)hbits)));
            if (!isfinite(ah) || ah > 16.f) ah = 16.f;
            if (ah < 1e-6f) ah = 1e-6f;
            m[1] += 0.5f * ah;
            float ab = fabsf(__uint_as_float(hbits << 16));
            if (!isfinite(ab) || ab > 16.f) ab = 16.f;
            if (ab < 1e-6f) ab = 1e-6f;
            m[2] += 0.5f * ab;
        }
    }
    int best = 0;
    float bd = 1e30f;
    for (int k = 0; k < 3; ++k) {
        float d = fabsf(logf((m[k] * (1.0f / 128.0f)) / 0.798f));
        if (d < bd) { bd = d; best = k; }
    }
    g_xdt = best;
}

// ================= FAST PATH: W int32, x/scales/bias/out fp32 =================
// Coalesced staging: warp w, LDG j (j=0..3) covers row-pair p = w*4+j:
//   lanes 0-15  -> row 2p   bytes lane*16      (256B contiguous, 2 lines)
//   lanes 16-31 -> row 2p+1 bytes (lane-16)*16 (2 lines)            => 4 lines/LDG
__global__ void __launch_bounds__(THREADS, 3)
qlin_fast_kernel(const float* __restrict__ x,
                 const int* __restrict__ qw,
                 const float* __restrict__ scales,
                 const float* __restrict__ bias,
                 float* __restrict__ out)
{
    if (!(g_qint32 == 1 && g_xdt == 0)) return;

    extern __shared__ char smem_raw[];
    const uint32_t sb = (smem_u32(smem_raw) + 1023u) & ~1023u;
    const uint32_t aoff[2] = {sb + F_OFF_A0, sb + F_OFF_A1};
    const uint32_t boff[2] = {sb + F_OFF_B0, sb + F_OFF_B1};

    const int tid  = threadIdx.x;
    const int wid  = tid >> 5;
    const int lane = tid & 31;
    const int row0 = blockIdx.x * FTILE_M;

    const int hi  = lane >> 4;        // which row of the pair
    const int sub = lane & 15;        // 16B segment within the 256B row-chunk

    // per-j base pointers (element offset of the 16B piece this thread loads)
    const int*   wb[4];
    const float* xb[4];
    uint32_t a_sts[4], b_sts[4];      // swizzled STS addresses (buffer-relative)
#pragma unroll
    for (int j = 0; j < 4; ++j) {
        const int p = wid * 4 + j;            // 0..15 row/token pair
        const int wrow = 2 * p + hi;          // 0..31 local row & token
        wb[j] = qw + (size_t)(row0 + wrow) * IN_F + sub * 4;
        xb[j] = x  + (size_t)wrow * IN_F + sub * 4;
        a_sts[j] = swz((uint32_t)(wrow * 128 + sub * 8));
        b_sts[j] = swz((uint32_t)(wrow * 128 + sub * 8));
    }

    // depth-2 register prefetch: 4 W + 4 X uint4 per stage
    uint4 wr[2][4], xr[2][4];
#pragma unroll
    for (int s = 0; s < 2; ++s)
#pragma unroll
        for (int j = 0; j < 4; ++j) {
            wr[s][j] = *(const uint4*)(wb[j] + s * KC);
            xr[s][j] = *(const uint4*)(xb[j] + s * KC);
        }

    float acc[2][4];   // 2 token-tiles (8 tokens each) x 4 c-regs
#pragma unroll
    for (int i = 0; i < 2; ++i)
#pragma unroll
        for (int j = 0; j < 4; ++j) acc[i][j] = 0.0f;

    // ldmatrix per-lane addressing
    const int am = lane >> 3;
    const uint32_t a_noswz = (uint32_t)(((wid & 1) * 16 + (am & 1) * 8 + (lane & 7)) * 128 +
                                        (am >> 1) * 16);
    const uint32_t b_noswz = (uint32_t)(((wid >> 1) * 16 + (am >> 1) * 8 + (lane & 7)) * 128 +
                                        (am & 1) * 16);

#pragma unroll 1
    for (int c = 0; c < NCHUNK; ++c) {
        const int s = c & 1;

        // ---- convert + STS ----
#pragma unroll
        for (int j = 0; j < 4; ++j) {
            // W: 4 int32 -> 4 int8 bytes -> exact fp16 pair-of-pairs
            uint32_t t1, t2, pk;
            asm("prmt.b32 %0, %1, %2, 0x0040;" : "=r"(t1) : "r"(wr[s][j].x), "r"(wr[s][j].y));
            asm("prmt.b32 %0, %1, %2, 0x0040;" : "=r"(t2) : "r"(wr[s][j].z), "r"(wr[s][j].w));
            asm("prmt.b32 %0, %1, %2, 0x5410;" : "=r"(pk) : "r"(t1), "r"(t2));
            uint32_t u = pk ^ 0x80808080u;
            uint32_t lo, hh, h0, h1;
            asm("prmt.b32 %0, %1, %2, 0x5140;" : "=r"(lo) : "r"(u), "r"(0x64646464u));
            asm("prmt.b32 %0, %1, %2, 0x7362;" : "=r"(hh) : "r"(u), "r"(0x64646464u));
            asm("sub.rn.f16x2 %0, %1, %2;" : "=r"(h0) : "r"(lo), "r"(0x64806480u));
            asm("sub.rn.f16x2 %0, %1, %2;" : "=r"(h1) : "r"(hh), "r"(0x64806480u));
            asm volatile("st.shared.v2.b32 [%0], {%1, %2};"
                         :: "r"(aoff[s] + a_sts[j]), "r"(h0), "r"(h1) : "memory");

            // X: 4 fp32 -> 2 fp16x2
            __half2 p0 = __floats2half2_rn(__uint_as_float(xr[s][j].x),
                                           __uint_as_float(xr[s][j].y));
            __half2 p1 = __floats2half2_rn(__uint_as_float(xr[s][j].z),
                                           __uint_as_float(xr[s][j].w));
            asm volatile("st.shared.v2.b32 [%0], {%1, %2};"
                         :: "r"(boff[s] + b_sts[j]),
                            "r"(*(uint32_t*)&p0), "r"(*(uint32_t*)&p1) : "memory");
        }

        __syncthreads();   // STS(c) visible; transitively fences buffer reuse

        // prefetch chunk c+2 into the register set just consumed
        if (c + 2 < NCHUNK) {
            const int k2 = (c + 2) * KC;
#pragma unroll
            for (int j = 0; j < 4; ++j) {
                wr[s][j] = *(const uint4*)(wb[j] + k2);
                xr[s][j] = *(const uint4*)(xb[j] + k2);
            }
        }

        // ---- compute: 4 k-steps, 1 A-ldsm + 1 B-ldsm + 2 MMA each ----
        const uint32_t ab = aoff[s], bb = boff[s];
#pragma unroll
        for (int ks = 0; ks < 4; ++ks) {
            const uint32_t kbyte = (uint32_t)(ks * 32);
            uint32_t a0, a1, a2, a3;
            ldsm_x4(a0, a1, a2, a3, ab + swz(a_noswz + kbyte));
            uint32_t b0, b1, b2, b3;
            ldsm_x4(b0, b1, b2, b3, bb + swz(b_noswz + kbyte));
            mma16816(acc[0], a0, a1, a2, a3, b0, b1);   // tokens ntbase+0..7
            mma16816(acc[1], a0, a1, a2, a3, b2, b3);   // tokens ntbase+8..15
        }
    }

    // ---- epilogue ----
    const int g = lane >> 2, tig = lane & 3;
    const int o0 = row0 + (wid & 1) * 16 + g;
    const int o1 = o0 + 8;
    const int ntbase = (wid >> 1) * 16;
    const float s0 = scales[o0], bi0 = bias[o0];
    const float s1 = scales[o1], bi1 = bias[o1];

#pragma unroll
    for (int nt = 0; nt < 2; ++nt) {
        const int t0 = ntbase + nt * 8 + tig * 2;
        out[(size_t)t0       * OUT_F + o0] = acc[nt][0] * s0 + bi0;
        out[(size_t)(t0 + 1) * OUT_F + o0] = acc[nt][1] * s0 + bi0;
        out[(size_t)t0       * OUT_F + o1] = acc[nt][2] * s1 + bi1;
        out[(size_t)(t0 + 1) * OUT_F + o1] = acc[nt][3] * s1 + bi1;
    }
}

// ================= GENERIC FALLBACK (previously passing kernel) =================
__global__ void __launch_bounds__(THREADS, 2)
qlin_mma_kernel(const void* __restrict__ xv,
                const void* __restrict__ qwv,
                const void* __restrict__ scalesv,
                const void* __restrict__ biasv,
                void* __restrict__ outv)
{
    if (g_qint32 == 1 && g_xdt == 0) return;   // fast path handles this combo

    extern __shared__ char smem_raw[];
    const uint32_t sb = (smem_u32(smem_raw) + 1023u) & ~1023u;
    const uint32_t aoff[2] = {sb + OFF_A0, sb + OFF_A1};
    const uint32_t boff[2] = {sb + OFF_B0, sb + OFF_B1};

    const int q32 = g_qint32;
    const int xdt = g_xdt;

    const int tid  = threadIdx.x;
    const int wid  = tid >> 5;
    const int lane = tid & 31;
    const int row0 = blockIdx.x * TILE_M;

    const int r = tid >> 1, h = tid & 1;
    const int tok = tid >> 2, seg = tid & 3;

    const int8_t* w8base  = (const int8_t*)qwv + (size_t)(row0 + r) * IN_F + h * 32;
    const int*    w32base = (const int*)qwv    + (size_t)(row0 + r) * IN_F + h * 32;
    const __half* x16base = (const __half*)xv  + (size_t)tok * IN_F + seg * 16;
    const float*  x32base = (const float*)xv   + (size_t)tok * IN_F + seg * 16;

    uint4 wraw[2][8];
    uint4 xraw[2][4];

    auto load_w = [&](int s, int c) {
        if (q32) {
            const uint4* p = (const uint4*)(w32base + c * KC);
#pragma unroll
            for (int j = 0; j < 8; ++j) wraw[s][j] = p[j];
        } else {
            const uint4* p = (const uint4*)(w8base + c * KC);
            wraw[s][0] = p[0];
            wraw[s][1] = p[1];
        }
    };
    auto load_x = [&](int s, int c) {
        if (xdt == 0) {
            const uint4* p = (const uint4*)(x32base + (size_t)c * KC);
#pragma unroll
            for (int j = 0; j < 4; ++j) xraw[s][j] = p[j];
        } else {
            const uint4* p = (const uint4*)(x16base + (size_t)c * KC);
            xraw[s][0] = p[0];
            xraw[s][1] = p[1];
        }
    };

    load_w(0, 0); load_x(0, 0);
    load_w(1, 1); load_x(1, 1);

    float acc[4][4];
#pragma unroll
    for (int i = 0; i < 4; ++i)
#pragma unroll
        for (int j = 0; j < 4; ++j) acc[i][j] = 0.0f;

    const int am = lane >> 3;
    const uint32_t a_noswz =
        (uint32_t)((wid * 16 + (am & 1) * 8 + (lane & 7)) * 128 + (am >> 1) * 16);
    const uint32_t b_row_local =
        (uint32_t)(((am >> 1) * 8 + (lane & 7)) * 128 + (am & 1) * 16);

    const uint32_t a_sts_base = (uint32_t)(r * 128 + h * 64);
    const uint32_t b_sts_base = (uint32_t)(tok * 128 + seg * 32);

#pragma unroll 1
    for (int c = 0; c < NCHUNK; ++c) {
        const int s = c & 1;

        const uint32_t* wr = (const uint32_t*)wraw[s];
        uint32_t pk[8];
        if (q32) {
#pragma unroll
            for (int i = 0; i < 8; ++i) {
                uint32_t t1, t2;
                asm("prmt.b32 %0, %1, %2, 0x0040;" : "=r"(t1) : "r"(wr[4 * i]),     "r"(wr[4 * i + 1]));
                asm("prmt.b32 %0, %1, %2, 0x0040;" : "=r"(t2) : "r"(wr[4 * i + 2]), "r"(wr[4 * i + 3]));
                asm("prmt.b32 %0, %1, %2, 0x5410;" : "=r"(pk[i]) : "r"(t1), "r"(t2));
            }
        } else {
#pragma unroll
            for (int i = 0; i < 8; ++i) pk[i] = wr[i];
        }
        uint32_t o2[16];
#pragma unroll
        for (int i = 0; i < 8; ++i) {
            uint32_t u = pk[i] ^ 0x80808080u;
            uint32_t lo, hi2;
            asm("prmt.b32 %0, %1, %2, 0x5140;" : "=r"(lo)  : "r"(u), "r"(0x64646464u));
            asm("prmt.b32 %0, %1, %2, 0x7362;" : "=r"(hi2) : "r"(u), "r"(0x64646464u));
            asm("sub.rn.f16x2 %0, %1, %2;" : "=r"(o2[2 * i])     : "r"(lo),  "r"(0x64806480u));
            asm("sub.rn.f16x2 %0, %1, %2;" : "=r"(o2[2 * i + 1]) : "r"(hi2), "r"(0x64806480u));
        }
#pragma unroll
        for (int q = 0; q < 4; ++q) {
            uint32_t addr = aoff[s] + swz(a_sts_base + q * 16);
            asm volatile("st.shared.v4.b32 [%0], {%1,%2,%3,%4};"
                         :: "r"(addr), "r"(o2[4 * q]), "r"(o2[4 * q + 1]),
                            "r"(o2[4 * q + 2]), "r"(o2[4 * q + 3]) : "memory");
        }

        uint32_t xb2[8];
        const uint32_t* xr = (const uint32_t*)xraw[s];
        if (xdt == 1) {
#pragma unroll
            for (int j = 0; j < 8; ++j) xb2[j] = xr[j];
        } else if (xdt == 0) {
#pragma unroll
            for (int j = 0; j < 8; ++j) {
                __half2 hp = __floats2half2_rn(__uint_as_float(xr[2 * j]),
                                               __uint_as_float(xr[2 * j + 1]));
                xb2[j] = *(uint32_t*)&hp;
            }
        } else {
#pragma unroll
            for (int j = 0; j < 8; ++j) {
                uint32_t w = xr[j];
                __half2 hp = __floats2half2_rn(__uint_as_float(w << 16),
                                               __uint_as_float(w & 0xFFFF0000u));
                xb2[j] = *(uint32_t*)&hp;
            }
        }
#pragma unroll
        for (int j = 0; j < 2; ++j) {
            uint32_t addr = boff[s] + swz(b_sts_base + j * 16);
            asm volatile("st.shared.v4.b32 [%0], {%1,%2,%3,%4};"
                         :: "r"(addr), "r"(xb2[4 * j]), "r"(xb2[4 * j + 1]),
                            "r"(xb2[4 * j + 2]), "r"(xb2[4 * j + 3]) : "memory");
        }

        __syncthreads();

        if (c + 2 < NCHUNK) { load_w(s, c + 2); load_x(s, c + 2); }

        const uint32_t ab = aoff[s], bb = boff[s];
#pragma unroll
        for (int ks = 0; ks < 4; ++ks) {
            const uint32_t kbyte = (uint32_t)(ks * 32);
            uint32_t a0, a1, a2, a3;
            ldsm_x4(a0, a1, a2, a3, ab + swz(a_noswz + kbyte));
            uint32_t b0, b1, b2, b3;
            ldsm_x4(b0, b1, b2, b3, bb + swz(b_row_local + kbyte));
            uint32_t b4, b5, b6, b7;
            ldsm_x4(b4, b5, b6, b7, bb + swz(b_row_local + 16 * 128 + kbyte));
            mma16816(acc[0], a0, a1, a2, a3, b0, b1);
            mma16816(acc[1], a0, a1, a2, a3, b2, b3);
            mma16816(acc[2], a0, a1, a2, a3, b4, b5);
            mma16816(acc[3], a0, a1, a2, a3, b6, b7);
        }
    }

    const int g = lane >> 2, tig = lane & 3;
    const int o0 = row0 + wid * 16 + g;
    const int o1 = o0 + 8;

    float s0, s1, bi0, bi1;
    if (xdt == 0) {
        s0  = ((const float*)scalesv)[o0]; s1  = ((const float*)scalesv)[o1];
        bi0 = ((const float*)biasv)[o0];   bi1 = ((const float*)biasv)[o1];
    } else if (xdt == 1) {
        s0  = __half2float(((const __half*)scalesv)[o0]);
        s1  = __half2float(((const __half*)scalesv)[o1]);
        bi0 = __half2float(((const __half*)biasv)[o0]);
        bi1 = __half2float(((const __half*)biasv)[o1]);
    } else {
        s0  = __uint_as_float(((uint32_t)((const unsigned short*)scalesv)[o0]) << 16);
        s1  = __uint_as_float(((uint32_t)((const unsigned short*)scalesv)[o1]) << 16);
        bi0 = __uint_as_float(((uint32_t)((const unsigned short*)biasv)[o0]) << 16);
        bi1 = __uint_as_float(((uint32_t)((const unsigned short*)biasv)[o1]) << 16);
    }

#pragma unroll
    for (int nt = 0; nt < 4; ++nt) {
        const int t0 = nt * 8 + tig * 2;
        float v00 = acc[nt][0] * s0 + bi0;
        float v01 = acc[nt][1] * s0 + bi0;
        float v10 = acc[nt][2] * s1 + bi1;
        float v11 = acc[nt][3] * s1 + bi1;
        size_t i00 = (size_t)t0 * OUT_F + o0, i01 = i00 + OUT_F;
        size_t i10 = (size_t)t0 * OUT_F + o1, i11 = i10 + OUT_F;
        if (xdt == 0) {
            float* o = (float*)outv;
            o[i00] = v00; o[i01] = v01; o[i10] = v10; o[i11] = v11;
        } else if (xdt == 1) {
            __half* o = (__half*)outv;
            o[i00] = __float2half(v00); o[i01] = __float2half(v01);
            o[i10] = __float2half(v10); o[i11] = __float2half(v11);
        } else {
            __nv_bfloat16* o = (__nv_bfloat16*)outv;
            o[i00] = __float2bfloat16(v00); o[i01] = __float2bfloat16(v01);
            o[i10] = __float2bfloat16(v10); o[i11] = __float2bfloat16(v11);
        }
    }
}

extern "C" void kernel_launch(void* const* d_in, const int* in_sizes, int n_in,
                              void* d_out, int out_size) {
    const void* x      = d_in[0];
    const void* qw     = d_in[1];
    const void* scales = d_in[2];
    const void* bias   = d_in[3];

    detect_kernel<<<1, 32>>>(x, qw);

    dim3 fgrid(OUT_F / FTILE_M);   // 344 CTAs
    qlin_fast_kernel<<<fgrid, THREADS, F_SMEM>>>(
        (const float*)x, (const int*)qw, (const float*)scales,
        (const float*)bias, (float*)d_out);

    dim3 ggrid(OUT_F / TILE_M);    // 172 CTAs (early-exits when fast path ran)
    qlin_mma_kernel<<<ggrid, THREADS, SMEM_BYTES>>>(x, qw, scales, bias, d_out);
}

// round 14
// speedup vs baseline: 3.5713x; 1.7603x over previous
#include <cuda_runtime.h>
#include <cuda_fp16.h>
#include <cuda_bf16.h>
#include <cstdint>

#define N_TOKENS 32
#define IN_F     4096
#define OUT_F    11008
#define KC       64
#define NCHUNK   (IN_F / KC)       // 64
#define THREADS  128               // 4 warps

// ---- fast-path (int32 W, fp32 x) config: TILE_M = 32 ----
#define FTILE_M  32
#define FA_BYTES (FTILE_M * 128)   // 4096
#define FX_BYTES (N_TOKENS * 128)  // 4096 per tile
// SMEM: A double (2x4096) + X quad ring (4x4096) + align pad
#define F_SMEM   (2 * FA_BYTES + 4 * FX_BYTES + 1024)   // 25600

// ---- generic fallback config: TILE_M = 64 ----
#define TILE_M   64
#define A_BYTES  (TILE_M * 128)
#define B_BYTES  (N_TOKENS * 128)
#define OFF_A0   0
#define OFF_B0   (A_BYTES)
#define OFF_A1   (A_BYTES + B_BYTES)
#define OFF_B1   (OFF_A1 + A_BYTES)
#define SMEM_BYTES (2 * (A_BYTES + B_BYTES) + 1024)

// runtime dtype flags
__device__ int g_qint32;   // 1: qweight int32, 0: int8
__device__ int g_xdt;      // 0: fp32, 1: fp16, 2: bf16

// pre-converted, pre-swizzled X tiles: [NCHUNK][4KB tile image]
__device__ __align__(16) unsigned char g_xtiles[NCHUNK * 4096];

// ---------------- helpers ----------------
__device__ __forceinline__ uint32_t smem_u32(const void* p) {
    uint32_t a;
    asm("{ .reg .u64 t; cvta.to.shared.u64 t, %1; cvt.u32.u64 %0, t; }" : "=r"(a) : "l"(p));
    return a;
}
__device__ __forceinline__ uint32_t swz(uint32_t off) {   // SW128: Swizzle<3,4,3>
    return off ^ ((off >> 3) & 0x70);
}
__device__ __forceinline__ void ldsm_x4(uint32_t& r0, uint32_t& r1, uint32_t& r2,
                                        uint32_t& r3, uint32_t addr) {
    asm volatile("ldmatrix.sync.aligned.m8n8.x4.shared.b16 {%0,%1,%2,%3}, [%4];"
                 : "=r"(r0), "=r"(r1), "=r"(r2), "=r"(r3) : "r"(addr));
}
__device__ __forceinline__ void mma16816(float* c, uint32_t a0, uint32_t a1,
                                         uint32_t a2, uint32_t a3,
                                         uint32_t b0, uint32_t b1) {
    asm volatile(
        "mma.sync.aligned.m16n8k16.row.col.f32.f16.f16.f32 "
        "{%0,%1,%2,%3}, {%4,%5,%6,%7}, {%8,%9}, {%0,%1,%2,%3};"
        : "+f"(c[0]), "+f"(c[1]), "+f"(c[2]), "+f"(c[3])
        : "r"(a0), "r"(a1), "r"(a2), "r"(a3), "r"(b0), "r"(b1));
}
__device__ __forceinline__ void cp_async16(uint32_t smem_dst, const void* gsrc) {
    asm volatile("cp.async.cg.shared.global [%0], [%1], 16;"
                 :: "r"(smem_dst), "l"(gsrc) : "memory");
}

// ---------------- dtype detection (parallel, deterministic decision) ----------------
__global__ void detect_kernel(const void* x, const void* qw) {
    __shared__ float s_m[3];
    const int tid = threadIdx.x;   // 128 threads
    if (tid < 3) s_m[tid] = 0.f;

    const int* qi = (const int*)qw;
    int ok = 1;
    if (tid < 64) {
        int v = qi[tid];
        ok = (v >= -128 && v <= 127);
    }
    __syncthreads();

    // x interpretation scores over the first 512 bytes
    uint32_t w = ((const uint32_t*)x)[tid];
    float a = fabsf(__uint_as_float(w));
    if (!isfinite(a) || a > 16.f) a = 16.f;
    if (a < 1e-6f) a = 1e-6f;
    float mh = 0.f, mb = 0.f;
#pragma unroll
    for (int hsel = 0; hsel < 2; ++hsel) {
        uint32_t hbits = (w >> (16 * hsel)) & 0xFFFFu;
        float ah = fabsf(__half2float(__ushort_as_half((unsigned short)hbits)));
        if (!isfinite(ah) || ah > 16.f) ah = 16.f;
        if (ah < 1e-6f) ah = 1e-6f;
        mh += 0.5f * ah;
        float ab = fabsf(__uint_as_float(hbits << 16));
        if (!isfinite(ab) || ab > 16.f) ab = 16.f;
        if (ab < 1e-6f) ab = 1e-6f;
        mb += 0.5f * ab;
    }
    atomicAdd(&s_m[0], a);
    atomicAdd(&s_m[1], mh);
    atomicAdd(&s_m[2], mb);

    int allok = __syncthreads_and(ok);

    if (tid == 0) {
        g_qint32 = allok ? 1 : 0;
        int best = 0;
        float bd = 1e30f;
#pragma unroll
        for (int k = 0; k < 3; ++k) {
            float d = fabsf(logf((s_m[k] * (1.0f / 128.0f)) / 0.798f));
            if (d < bd) { bd = d; best = k; }
        }
        g_xdt = best;
    }
}

// ---------------- xprep: fp32 X -> fp16, pre-swizzled per-chunk tile images ----------------
// Tile image layout (matches main kernel's B SMEM): half k of token t at byte
// t*128 + ((2k) ^ ((t&7)<<4)).
__global__ void xprep_kernel(const float* __restrict__ x) {
    if (!(g_qint32 == 1 && g_xdt == 0)) return;
    const int c   = blockIdx.x;        // chunk
    const int tid = threadIdx.x;       // 128
    const int tok = tid >> 2;
    const int q   = tid & 3;           // 16 floats each

    const float* xp = x + (size_t)tok * IN_F + c * KC + q * 16;
    uint4 f[4];
#pragma unroll
    for (int j = 0; j < 4; ++j) f[j] = ((const uint4*)xp)[j];

    uint32_t h[8];
#pragma unroll
    for (int j = 0; j < 4; ++j) {
        __half2 p0 = __floats2half2_rn(__uint_as_float(f[j].x), __uint_as_float(f[j].y));
        __half2 p1 = __floats2half2_rn(__uint_as_float(f[j].z), __uint_as_float(f[j].w));
        h[2 * j]     = *(uint32_t*)&p0;
        h[2 * j + 1] = *(uint32_t*)&p1;
    }
    unsigned char* base = g_xtiles + (size_t)c * 4096 + tok * 128;
    const uint32_t xorm = (uint32_t)((tok & 7) << 4);
    *(uint4*)(base + (((uint32_t)(q * 32))      ^ xorm)) = make_uint4(h[0], h[1], h[2], h[3]);
    *(uint4*)(base + (((uint32_t)(q * 32 + 16)) ^ xorm)) = make_uint4(h[4], h[5], h[6], h[7]);
}

// ================= FAST PATH: W int32, x/scales/bias/out fp32 =================
__global__ void __launch_bounds__(THREADS, 4)
qlin_fast_kernel(const float* __restrict__ x,
                 const int* __restrict__ qw,
                 const float* __restrict__ scales,
                 const float* __restrict__ bias,
                 float* __restrict__ out)
{
    if (!(g_qint32 == 1 && g_xdt == 0)) return;

    extern __shared__ char smem_raw[];
    const uint32_t sb = (smem_u32(smem_raw) + 1023u) & ~1023u;
    const uint32_t abuf[2] = {sb, sb + 4096};
    const uint32_t xbuf[4] = {sb + 8192, sb + 12288, sb + 16384, sb + 20480};

    const int tid  = threadIdx.x;
    const int wid  = tid >> 5;
    const int lane = tid & 31;
    const int row0 = blockIdx.x * FTILE_M;

    const int hi  = lane >> 4;
    const int sub = lane & 15;

    // W staging: warp w, j=0..3 -> row pair p=w*4+j; coalesced 4-line LDG.128
    const int* wb[4];
    uint32_t a_sts[4];
#pragma unroll
    for (int j = 0; j < 4; ++j) {
        const int p = wid * 4 + j;
        const int wrow = 2 * p + hi;
        wb[j] = qw + (size_t)(row0 + wrow) * IN_F + sub * 4;
        a_sts[j] = swz((uint32_t)(wrow * 128 + sub * 8));
    }

    // W prefetch depth 4
    uint4 wr[4][4];
#pragma unroll
    for (int s = 0; s < 4; ++s)
#pragma unroll
        for (int j = 0; j < 4; ++j)
            wr[s][j] = *(const uint4*)(wb[j] + s * KC);

    // pre-issue X tiles 0,1,2 (one commit group each)
    const unsigned char* xsrc = g_xtiles;
#pragma unroll
    for (int p = 0; p < 3; ++p) {
        cp_async16(xbuf[p] + tid * 32,      xsrc + (size_t)p * 4096 + tid * 32);
        cp_async16(xbuf[p] + tid * 32 + 16, xsrc + (size_t)p * 4096 + tid * 32 + 16);
        asm volatile("cp.async.commit_group;" ::: "memory");
    }

    float acc[2][4];
#pragma unroll
    for (int i = 0; i < 2; ++i)
#pragma unroll
        for (int j = 0; j < 4; ++j) acc[i][j] = 0.0f;

    // ldmatrix per-lane addressing (identical to R12 fast path)
    const int am = lane >> 3;
    const uint32_t a_noswz = (uint32_t)(((wid & 1) * 16 + (am & 1) * 8 + (lane & 7)) * 128 +
                                        (am >> 1) * 16);
    const uint32_t b_noswz = (uint32_t)(((wid >> 1) * 16 + (am >> 1) * 8 + (lane & 7)) * 128 +
                                        (am & 1) * 16);

#pragma unroll 1
    for (int cc = 0; cc < NCHUNK; cc += 4) {
#pragma unroll
        for (int u = 0; u < 4; ++u) {
            const int c = cc + u;

            // ---- convert W stage u -> STS A buf (u&1) ----
#pragma unroll
            for (int j = 0; j < 4; ++j) {
                uint32_t t1, t2, pk;
                asm("prmt.b32 %0, %1, %2, 0x0040;" : "=r"(t1) : "r"(wr[u][j].x), "r"(wr[u][j].y));
                asm("prmt.b32 %0, %1, %2, 0x0040;" : "=r"(t2) : "r"(wr[u][j].z), "r"(wr[u][j].w));
                asm("prmt.b32 %0, %1, %2, 0x5410;" : "=r"(pk) : "r"(t1), "r"(t2));
                uint32_t uu = pk ^ 0x80808080u;
                uint32_t lo, hh, h0, h1;
                asm("prmt.b32 %0, %1, %2, 0x5140;" : "=r"(lo) : "r"(uu), "r"(0x64646464u));
                asm("prmt.b32 %0, %1, %2, 0x7362;" : "=r"(hh) : "r"(uu), "r"(0x64646464u));
                asm("sub.rn.f16x2 %0, %1, %2;" : "=r"(h0) : "r"(lo), "r"(0x64806480u));
                asm("sub.rn.f16x2 %0, %1, %2;" : "=r"(h1) : "r"(hh), "r"(0x64806480u));
                asm volatile("st.shared.v2.b32 [%0], {%1, %2};"
                             :: "r"(abuf[u & 1] + a_sts[j]), "r"(h0), "r"(h1) : "memory");
            }

            // X tile c must be complete before the barrier (<=2 newer groups pending)
            asm volatile("cp.async.wait_group 2;" ::: "memory");
            __syncthreads();   // A STS + X tile visible; fences buffer reuse

            // ---- issue X tile c+3 into ring slot (u+3)&3 ----
            if (c + 3 < NCHUNK) {
                const unsigned char* s3 = xsrc + (size_t)(c + 3) * 4096 + tid * 32;
                cp_async16(xbuf[(u + 3) & 3] + tid * 32,      s3);
                cp_async16(xbuf[(u + 3) & 3] + tid * 32 + 16, s3 + 16);
            }
            asm volatile("cp.async.commit_group;" ::: "memory");

            // ---- prefetch W chunk c+4 into stage u ----
            if (c + 4 < NCHUNK) {
                const int k4 = (c + 4) * KC;
#pragma unroll
                for (int j = 0; j < 4; ++j)
                    wr[u][j] = *(const uint4*)(wb[j] + k4);
            }

            // ---- compute chunk c ----
            const uint32_t ab = abuf[u & 1], bbx = xbuf[u];
#pragma unroll
            for (int ks = 0; ks < 4; ++ks) {
                const uint32_t kbyte = (uint32_t)(ks * 32);
                uint32_t a0, a1, a2, a3;
                ldsm_x4(a0, a1, a2, a3, ab + swz(a_noswz + kbyte));
                uint32_t b0, b1, b2, b3;
                ldsm_x4(b0, b1, b2, b3, bbx + swz(b_noswz + kbyte));
                mma16816(acc[0], a0, a1, a2, a3, b0, b1);
                mma16816(acc[1], a0, a1, a2, a3, b2, b3);
            }
        }
    }

    // ---- epilogue ----
    const int g = lane >> 2, tig = lane & 3;
    const int o0 = row0 + (wid & 1) * 16 + g;
    const int o1 = o0 + 8;
    const int ntbase = (wid >> 1) * 16;
    const float s0 = scales[o0], bi0 = bias[o0];
    const float s1 = scales[o1], bi1 = bias[o1];

#pragma unroll
    for (int nt = 0; nt < 2; ++nt) {
        const int t0 = ntbase + nt * 8 + tig * 2;
        out[(size_t)t0       * OUT_F + o0] = acc[nt][0] * s0 + bi0;
        out[(size_t)(t0 + 1) * OUT_F + o0] = acc[nt][1] * s0 + bi0;
        out[(size_t)t0       * OUT_F + o1] = acc[nt][2] * s1 + bi1;
        out[(size_t)(t0 + 1) * OUT_F + o1] = acc[nt][3] * s1 + bi1;
    }
}

// ================= GENERIC FALLBACK (previously passing kernel, unchanged) =================
__global__ void __launch_bounds__(THREADS, 2)
qlin_mma_kernel(const void* __restrict__ xv,
                const void* __restrict__ qwv,
                const void* __restrict__ scalesv,
                const void* __restrict__ biasv,
                void* __restrict__ outv)
{
    if (g_qint32 == 1 && g_xdt == 0) return;   // fast path handles this combo

    extern __shared__ char smem_raw[];
    const uint32_t sb = (smem_u32(smem_raw) + 1023u) & ~1023u;
    const uint32_t aoff[2] = {sb + OFF_A0, sb + OFF_A1};
    const uint32_t boff[2] = {sb + OFF_B0, sb + OFF_B1};

    const int q32 = g_qint32;
    const int xdt = g_xdt;

    const int tid  = threadIdx.x;
    const int wid  = tid >> 5;
    const int lane = tid & 31;
    const int row0 = blockIdx.x * TILE_M;

    const int r = tid >> 1, h = tid & 1;
    const int tok = tid >> 2, seg = tid & 3;

    const int8_t* w8base  = (const int8_t*)qwv + (size_t)(row0 + r) * IN_F + h * 32;
    const int*    w32base = (const int*)qwv    + (size_t)(row0 + r) * IN_F + h * 32;
    const __half* x16base = (const __half*)xv  + (size_t)tok * IN_F + seg * 16;
    const float*  x32base = (const float*)xv   + (size_t)tok * IN_F + seg * 16;

    uint4 wraw[2][8];
    uint4 xraw[2][4];

    auto load_w = [&](int s, int c) {
        if (q32) {
            const uint4* p = (const uint4*)(w32base + c * KC);
#pragma unroll
            for (int j = 0; j < 8; ++j) wraw[s][j] = p[j];
        } else {
            const uint4* p = (const uint4*)(w8base + c * KC);
            wraw[s][0] = p[0];
            wraw[s][1] = p[1];
        }
    };
    auto load_x = [&](int s, int c) {
        if (xdt == 0) {
            const uint4* p = (const uint4*)(x32base + (size_t)c * KC);
#pragma unroll
            for (int j = 0; j < 4; ++j) xraw[s][j] = p[j];
        } else {
            const uint4* p = (const uint4*)(x16base + (size_t)c * KC);
            xraw[s][0] = p[0];
            xraw[s][1] = p[1];
        }
    };

    load_w(0, 0); load_x(0, 0);
    load_w(1, 1); load_x(1, 1);

    float acc[4][4];
#pragma unroll
    for (int i = 0; i < 4; ++i)
#pragma unroll
        for (int j = 0; j < 4; ++j) acc[i][j] = 0.0f;

    const int am = lane >> 3;
    const uint32_t a_noswz =
        (uint32_t)((wid * 16 + (am & 1) * 8 + (lane & 7)) * 128 + (am >> 1) * 16);
    const uint32_t b_row_local =
        (uint32_t)(((am >> 1) * 8 + (lane & 7)) * 128 + (am & 1) * 16);

    const uint32_t a_sts_base = (uint32_t)(r * 128 + h * 64);
    const uint32_t b_sts_base = (uint32_t)(tok * 128 + seg * 32);

#pragma unroll 1
    for (int c = 0; c < NCHUNK; ++c) {
        const int s = c & 1;

        const uint32_t* wrp = (const uint32_t*)wraw[s];
        uint32_t pk[8];
        if (q32) {
#pragma unroll
            for (int i = 0; i < 8; ++i) {
                uint32_t t1, t2;
                asm("prmt.b32 %0, %1, %2, 0x0040;" : "=r"(t1) : "r"(wrp[4 * i]),     "r"(wrp[4 * i + 1]));
                asm("prmt.b32 %0, %1, %2, 0x0040;" : "=r"(t2) : "r"(wrp[4 * i + 2]), "r"(wrp[4 * i + 3]));
                asm("prmt.b32 %0, %1, %2, 0x5410;" : "=r"(pk[i]) : "r"(t1), "r"(t2));
            }
        } else {
#pragma unroll
            for (int i = 0; i < 8; ++i) pk[i] = wrp[i];
        }
        uint32_t o2[16];
#pragma unroll
        for (int i = 0; i < 8; ++i) {
            uint32_t u = pk[i] ^ 0x80808080u;
            uint32_t lo, hi2;
            asm("prmt.b32 %0, %1, %2, 0x5140;" : "=r"(lo)  : "r"(u), "r"(0x64646464u));
            asm("prmt.b32 %0, %1, %2, 0x7362;" : "=r"(hi2) : "r"(u), "r"(0x64646464u));
            asm("sub.rn.f16x2 %0, %1, %2;" : "=r"(o2[2 * i])     : "r"(lo),  "r"(0x64806480u));
            asm("sub.rn.f16x2 %0, %1, %2;" : "=r"(o2[2 * i + 1]) : "r"(hi2), "r"(0x64806480u));
        }
#pragma unroll
        for (int q = 0; q < 4; ++q) {
            uint32_t addr = aoff[s] + swz(a_sts_base + q * 16);
            asm volatile("st.shared.v4.b32 [%0], {%1,%2,%3,%4};"
                         :: "r"(addr), "r"(o2[4 * q]), "r"(o2[4 * q + 1]),
                            "r"(o2[4 * q + 2]), "r"(o2[4 * q + 3]) : "memory");
        }

        uint32_t xb2[8];
        const uint32_t* xr = (const uint32_t*)xraw[s];
        if (xdt == 1) {
#pragma unroll
            for (int j = 0; j < 8; ++j) xb2[j] = xr[j];
        } else if (xdt == 0) {
#pragma unroll
            for (int j = 0; j < 8; ++j) {
                __half2 hp = __floats2half2_rn(__uint_as_float(xr[2 * j]),
                                               __uint_as_float(xr[2 * j + 1]));
                xb2[j] = *(uint32_t*)&hp;
            }
        } else {
#pragma unroll
            for (int j = 0; j < 8; ++j) {
                uint32_t w = xr[j];
                __half2 hp = __floats2half2_rn(__uint_as_float(w << 16),
                                               __uint_as_float(w & 0xFFFF0000u));
                xb2[j] = *(uint32_t*)&hp;
            }
        }
#pragma unroll
        for (int j = 0; j < 2; ++j) {
            uint32_t addr = boff[s] + swz(b_sts_base + j * 16);
            asm volatile("st.shared.v4.b32 [%0], {%1,%2,%3,%4};"
                         :: "r"(addr), "r"(xb2[4 * j]), "r"(xb2[4 * j + 1]),
                            "r"(xb2[4 * j + 2]), "r"(xb2[4 * j + 3]) : "memory");
        }

        __syncthreads();

        if (c + 2 < NCHUNK) { load_w(s, c + 2); load_x(s, c + 2); }

        const uint32_t ab = aoff[s], bb = boff[s];
#pragma unroll
        for (int ks = 0; ks < 4; ++ks) {
            const uint32_t kbyte = (uint32_t)(ks * 32);
            uint32_t a0, a1, a2, a3;
            ldsm_x4(a0, a1, a2, a3, ab + swz(a_noswz + kbyte));
            uint32_t b0, b1, b2, b3;
            ldsm_x4(b0, b1, b2, b3, bb + swz(b_row_local + kbyte));
            uint32_t b4, b5, b6, b7;
            ldsm_x4(b4, b5, b6, b7, bb + swz(b_row_local + 16 * 128 + kbyte));
            mma16816(acc[0], a0, a1, a2, a3, b0, b1);
            mma16816(acc[1], a0, a1, a2, a3, b2, b3);
            mma16816(acc[2], a0, a1, a2, a3, b4, b5);
            mma16816(acc[3], a0, a1, a2, a3, b6, b7);
        }
    }

    const int g = lane >> 2, tig = lane & 3;
    const int o0 = row0 + wid * 16 + g;
    const int o1 = o0 + 8;

    float s0, s1, bi0, bi1;
    if (xdt == 0) {
        s0  = ((const float*)scalesv)[o0]; s1  = ((const float*)scalesv)[o1];
        bi0 = ((const float*)biasv)[o0];   bi1 = ((const float*)biasv)[o1];
    } else if (xdt == 1) {
        s0  = __half2float(((const __half*)scalesv)[o0]);
        s1  = __half2float(((const __half*)scalesv)[o1]);
        bi0 = __half2float(((const __half*)biasv)[o0]);
        bi1 = __half2float(((const __half*)biasv)[o1]);
    } else {
        s0  = __uint_as_float(((uint32_t)((const unsigned short*)scalesv)[o0]) << 16);
        s1  = __uint_as_float(((uint32_t)((const unsigned short*)scalesv)[o1]) << 16);
        bi0 = __uint_as_float(((uint32_t)((const unsigned short*)biasv)[o0]) << 16);
        bi1 = __uint_as_float(((uint32_t)((const unsigned short*)biasv)[o1]) << 16);
    }

#pragma unroll
    for (int nt = 0; nt < 4; ++nt) {
        const int t0 = nt * 8 + tig * 2;
        float v00 = acc[nt][0] * s0 + bi0;
        float v01 = acc[nt][1] * s0 + bi0;
        float v10 = acc[nt][2] * s1 + bi1;
        float v11 = acc[nt][3] * s1 + bi1;
        size_t i00 = (size_t)t0 * OUT_F + o0, i01 = i00 + OUT_F;
        size_t i10 = (size_t)t0 * OUT_F + o1, i11 = i10 + OUT_F;
        if (xdt == 0) {
            float* o = (float*)outv;
            o[i00] = v00; o[i01] = v01; o[i10] = v10; o[i11] = v11;
        } else if (xdt == 1) {
            __half* o = (__half*)outv;
            o[i00] = __float2half(v00); o[i01] = __float2half(v01);
            o[i10] = __float2half(v10); o[i11] = __float2half(v11);
        } else {
            __nv_bfloat16* o = (__nv_bfloat16*)outv;
            o[i00] = __float2bfloat16(v00); o[i01] = __float2bfloat16(v01);
            o[i10] = __float2bfloat16(v10); o[i11] = __float2bfloat16(v11);
        }
    }
}

extern "C" void kernel_launch(void* const* d_in, const int* in_sizes, int n_in,
                              void* d_out, int out_size) {
    const void* x      = d_in[0];
    const void* qw     = d_in[1];
    const void* scales = d_in[2];
    const void* bias   = d_in[3];

    detect_kernel<<<1, 128>>>(x, qw);
    xprep_kernel<<<NCHUNK, 128>>>((const float*)x);

    dim3 fgrid(OUT_F / FTILE_M);   // 344 CTAs
    qlin_fast_kernel<<<fgrid, THREADS, F_SMEM>>>(
        (const float*)x, (const int*)qw, (const float*)scales,
        (const float*)bias, (float*)d_out);

    dim3 ggrid(OUT_F / TILE_M);    // 172 CTAs (early-exits when fast path ran)
    qlin_mma_kernel<<<ggrid, THREADS, SMEM_BYTES>>>(x, qw, scales, bias, d_out);
}